// round 1
// baseline (speedup 1.0000x reference)
#include <cuda_runtime.h>

#define NN 50000
#define EE 800000
#define MAXPOS 5120

// ---------------- device scratch (allocation-free rule) ----------------
__device__ float d_Cbuf[7001 * 576];   // per text-id row: [TL(256) | TR(256) | TL2(32) | TR2(32)]
__device__ float d_Bpack[64 * 576];    // packed B for the table GEMM
__device__ float d_pe[128];
__device__ float d_ea[4][128];         // t=0..2 edge types, 3 = self-loop (mean) row
__device__ float d_we1[4][256];
__device__ float d_we2[4][32];
__device__ float d_TyL[3][256];
__device__ float d_TyR[3][256];
__device__ float d_TyL2[3][32];
__device__ float d_TyR2[3][32];
__device__ float d_cl[32];
__device__ float d_cr[32];
__device__ int   d_cnt[4];
__device__ int   d_px[NN];
__device__ int   d_deg[NN];
__device__ int   d_rowptr[NN + 1];
__device__ int   d_cursor[NN + 1];
__device__ int   d_bsum[64];
__device__ int   d_csr1[EE];           // x0s | x1s<<13 | t<<15   (layer-1: no pointer chase)
__device__ int   d_csr2[EE];           // s | t<<20               (layer-2 needs node id)
__device__ float d_xl2[NN * 32];
__device__ float d_xr2[NN * 32];
__device__ float d_gsum[32];

// ---------------- helpers ----------------
__device__ __forceinline__ float warp_sum(float v) {
#pragma unroll
    for (int o = 16; o > 0; o >>= 1) v += __shfl_xor_sync(0xffffffffu, v, o);
    return v;
}
__device__ __forceinline__ float lrelu(float x) {
    return fmaxf(x, 0.f) + 0.2f * fminf(x, 0.f);
}

// ---------------- small kernels ----------------
__global__ void k_zero(int n) {
    int i = blockIdx.x * 256 + threadIdx.x;
    if (i < n)  d_deg[i] = 0;
    if (i < 4)  d_cnt[i] = 0;
    if (i < 32) d_gsum[i] = 0.f;
}

__global__ void k_px(const int* __restrict__ x, int n) {
    int i = blockIdx.x * 256 + threadIdx.x;
    if (i < n) d_px[i] = x[2 * i] | (x[2 * i + 1] << 13);
}

__global__ void k_count(const int* __restrict__ ei, const int* __restrict__ ea, int E) {
    __shared__ int c[3];
    if (threadIdx.x < 3) c[threadIdx.x] = 0;
    __syncthreads();
    int e = blockIdx.x * 256 + threadIdx.x;
    if (e < E) {
        atomicAdd(&d_deg[ei[E + e]], 1);
        atomicAdd(&c[ea[2 * e]], 1);
    }
    __syncthreads();
    if (threadIdx.x < 3) atomicAdd(&d_cnt[threadIdx.x], c[threadIdx.x]);
}

__global__ void k_scan1(int n) {
    __shared__ int wsum[32];
    int i = blockIdx.x * 1024 + threadIdx.x;
    int lane = threadIdx.x & 31, wid = threadIdx.x >> 5;
    int x = (i < n) ? d_deg[i] : 0;
#pragma unroll
    for (int o = 1; o < 32; o <<= 1) {
        int y = __shfl_up_sync(0xffffffffu, x, o);
        if (lane >= o) x += y;
    }
    if (lane == 31) wsum[wid] = x;
    __syncthreads();
    if (wid == 0) {
        int s = wsum[lane];
#pragma unroll
        for (int o = 1; o < 32; o <<= 1) {
            int y = __shfl_up_sync(0xffffffffu, s, o);
            if (lane >= o) s += y;
        }
        wsum[lane] = s;
    }
    __syncthreads();
    int incl = x + (wid > 0 ? wsum[wid - 1] : 0);
    if (i < n) d_rowptr[i + 1] = incl;
    if (threadIdx.x == 1023) d_bsum[blockIdx.x] = incl;
}

__global__ void k_scan2(int nb) {
    if (threadIdx.x == 0 && blockIdx.x == 0) {
        int run = 0;
        for (int b = 0; b < nb; b++) { int t = d_bsum[b]; d_bsum[b] = run; run += t; }
    }
}

__global__ void k_scan3(int n) {
    int i = blockIdx.x * 1024 + threadIdx.x;
    int off = d_bsum[blockIdx.x];
    if (i < n) {
        int val = d_rowptr[i + 1] + off;
        d_rowptr[i + 1] = val;
        d_cursor[i + 1] = val;
    }
    if (i == 0) { d_rowptr[0] = 0; d_cursor[0] = 0; }
}

__global__ void k_fill(const int* __restrict__ ei, const int* __restrict__ ea, int E) {
    int e = blockIdx.x * 256 + threadIdx.x;
    if (e < E) {
        int s = ei[e];
        int d = ei[E + e];
        int t = ea[2 * e];
        int pos = atomicAdd(&d_cursor[d], 1);
        d_csr1[pos] = d_px[s] | (t << 15);
        d_csr2[pos] = s | (t << 20);
    }
}

// ---------------- precompute of all small derived tables ----------------
__global__ void k_pre(const float* __restrict__ pos_table, const float* __restrict__ pos_W,
                      const float* __restrict__ pos_b, const float* __restrict__ flow_emb,
                      const float* __restrict__ type_emb,
                      const float* __restrict__ c1_Wl, const float* __restrict__ c1_bl,
                      const float* __restrict__ c1_Wr, const float* __restrict__ c1_br,
                      const float* __restrict__ c1_We, const float* __restrict__ c2_We,
                      const float* __restrict__ c2_Wl, const float* __restrict__ c2_Wr,
                      const float* __restrict__ c1_bias,
                      const float* __restrict__ c2_bl, const float* __restrict__ c2_br,
                      int E) {
    int t = threadIdx.x;  // 256 threads
    // pe = pos_table[MAXPOS] @ pos_W + pos_b  (pos is provably always MAXPOS)
    if (t < 128) {
        const float* pr = pos_table + MAXPOS * 128;
        float s = pos_b[t];
        for (int k = 0; k < 128; k++) s += pr[k] * pos_W[k * 128 + t];
        d_pe[t] = s;
    }
    __syncthreads();
    if (t < 128) {
        float pe = d_pe[t];
        float invE = 1.f / (float)E;
        for (int ty = 0; ty < 3; ty++) d_ea[ty][t] = flow_emb[ty * 128 + t] + pe;
        d_ea[3][t] = pe + ((float)d_cnt[0] * flow_emb[t] +
                           (float)d_cnt[1] * flow_emb[128 + t] +
                           (float)d_cnt[2] * flow_emb[256 + t]) * invE;
    }
    // TyL'/TyR' = type_emb @ W*_bottom + bias
    {
        for (int ty = 0; ty < 3; ty++) {
            float sl = c1_bl[t], sr = c1_br[t];
            for (int k = 0; k < 64; k++) {
                float te = type_emb[ty * 64 + k];
                sl += te * c1_Wl[(64 + k) * 256 + t];
                sr += te * c1_Wr[(64 + k) * 256 + t];
            }
            d_TyL[ty][t] = sl; d_TyR[ty][t] = sr;
        }
    }
    __syncthreads();
    // we1/we2 = ea_t @ We (per edge type + self-loop row)
    {
        for (int ty = 0; ty < 4; ty++) {
            float s = 0.f;
            for (int k = 0; k < 128; k++) s += d_ea[ty][k] * c1_We[k * 256 + t];
            d_we1[ty][t] = s;
        }
    }
    if (t < 32) {
        for (int ty = 0; ty < 4; ty++) {
            float s = 0.f;
            for (int k = 0; k < 128; k++) s += d_ea[ty][k] * c2_We[k * 32 + t];
            d_we2[ty][t] = s;
        }
        // cl/cr = c1_bias @ Wl2/Wr2 + bl2/br2
        float sl = c2_bl[t], sr = c2_br[t];
        for (int k = 0; k < 256; k++) {
            float b = c1_bias[k];
            sl += b * c2_Wl[k * 32 + t];
            sr += b * c2_Wr[k * 32 + t];
        }
        d_cl[t] = sl; d_cr[t] = sr;
    }
    __syncthreads();
    // TyL2'/TyR2' = TyL' @ Wl2 / Wr2  (layer-2 value path derives from xl1)
    if (t < 96) {
        int ty = t >> 5, c = t & 31;
        float sl = 0.f, sr = 0.f;
        for (int k = 0; k < 256; k++) {
            float x = d_TyL[ty][k];
            sl += x * c2_Wl[k * 32 + c];
            sr += x * c2_Wr[k * 32 + c];
        }
        d_TyL2[ty][c] = sl; d_TyR2[ty][c] = sr;
    }
    // pack Wl_top | Wr_top into Bpack cols [0,512)
    for (int i = t; i < 64 * 512; i += 256) {
        int k = i >> 9, j = i & 511;
        d_Bpack[k * 576 + j] = (j < 256) ? c1_Wl[k * 256 + j] : c1_Wr[k * 256 + (j - 256)];
    }
}

// M_l = Wl1_top @ Wl2, M_r = Wl1_top @ Wr2 -> Bpack cols [512,576)
__global__ void k_prem(const float* __restrict__ c1_Wl,
                       const float* __restrict__ c2_Wl, const float* __restrict__ c2_Wr) {
    const float* W2 = (blockIdx.x == 0) ? c2_Wl : c2_Wr;
    int t = threadIdx.x;
    for (int i = t; i < 2048; i += 256) {
        int k = i >> 5, c = i & 31;
        float s = 0.f;
        const float* wrow = c1_Wl + k * 256;
        for (int j = 0; j < 256; j++) s += wrow[j] * W2[j * 32 + c];
        d_Bpack[k * 576 + 512 + blockIdx.x * 32 + c] = s;
    }
}

// Cbuf = text_emb (Mt x 64) @ Bpack (64 x 576)
__global__ void __launch_bounds__(256) k_tables(const float* __restrict__ A, int M) {
    __shared__ __align__(16) float As[64][64];
    __shared__ __align__(16) float Bs[64][64];
    int r0 = blockIdx.x * 64, c0 = blockIdx.y * 64;
    int tid = threadIdx.x;
    for (int idx = tid; idx < 4096; idx += 256) {
        int r = idx >> 6, k = idx & 63;
        As[r][k] = (r0 + r < M) ? A[(r0 + r) * 64 + k] : 0.f;
        Bs[r][k] = d_Bpack[r * 576 + c0 + k];  // r = k-dim, k = col
    }
    __syncthreads();
    int tx = tid & 15, ty = tid >> 4;
    float acc[4][4] = {};
#pragma unroll 4
    for (int k = 0; k < 64; k++) {
        float a0 = As[ty * 4 + 0][k], a1 = As[ty * 4 + 1][k];
        float a2 = As[ty * 4 + 2][k], a3 = As[ty * 4 + 3][k];
        float4 b = *(const float4*)&Bs[k][tx * 4];
        acc[0][0] += a0 * b.x; acc[0][1] += a0 * b.y; acc[0][2] += a0 * b.z; acc[0][3] += a0 * b.w;
        acc[1][0] += a1 * b.x; acc[1][1] += a1 * b.y; acc[1][2] += a1 * b.z; acc[1][3] += a1 * b.w;
        acc[2][0] += a2 * b.x; acc[2][1] += a2 * b.y; acc[2][2] += a2 * b.z; acc[2][3] += a2 * b.w;
        acc[3][0] += a3 * b.x; acc[3][1] += a3 * b.y; acc[3][2] += a3 * b.z; acc[3][3] += a3 * b.w;
    }
#pragma unroll
    for (int i = 0; i < 4; i++) {
        int r = r0 + ty * 4 + i;
        if (r < M) {
            float4 v = make_float4(acc[i][0], acc[i][1], acc[i][2], acc[i][3]);
            *(float4*)&d_Cbuf[r * 576 + c0 + tx * 4] = v;
        }
    }
}

// ---------------- layer 1: one warp per dst, online softmax ----------------
__global__ void __launch_bounds__(256) k_edge1(const float* __restrict__ att, int n) {
    __shared__ __align__(16) float s_we[4][256];
    __shared__ __align__(16) float s_TyL[3][256];
    __shared__ __align__(16) float s_TyR[3][256];
    __shared__ float s_TyL2[3][32];
    __shared__ float s_TyR2[3][32];
    int tid = threadIdx.x;
    for (int i = tid; i < 1024; i += 256) ((float*)s_we)[i] = ((const float*)d_we1)[i];
    for (int i = tid; i < 768; i += 256) {
        ((float*)s_TyL)[i] = ((const float*)d_TyL)[i];
        ((float*)s_TyR)[i] = ((const float*)d_TyR)[i];
    }
    if (tid < 96) {
        ((float*)s_TyL2)[tid] = ((const float*)d_TyL2)[tid];
        ((float*)s_TyR2)[tid] = ((const float*)d_TyR2)[tid];
    }
    __syncthreads();
    int lane = tid & 31;
    int v = blockIdx.x * 8 + (tid >> 5);
    if (v >= n) return;
    int j0 = lane * 8;

    int pv = d_px[v];
    int x0v = pv & 8191, x1v = pv >> 13;
    const float* rowv = d_Cbuf + x0v * 576;

    float xr[8], av[8];
    {
        float4 r0 = *(const float4*)(rowv + 256 + j0);
        float4 r1 = *(const float4*)(rowv + 260 + j0);
        float4 t0 = *(const float4*)(&s_TyR[x1v][j0]);
        float4 t1 = *(const float4*)(&s_TyR[x1v][j0 + 4]);
        xr[0] = r0.x + t0.x; xr[1] = r0.y + t0.y; xr[2] = r0.z + t0.z; xr[3] = r0.w + t0.w;
        xr[4] = r1.x + t1.x; xr[5] = r1.y + t1.y; xr[6] = r1.z + t1.z; xr[7] = r1.w + t1.w;
        float4 a0 = *(const float4*)(att + j0);
        float4 a1 = *(const float4*)(att + j0 + 4);
        av[0] = a0.x; av[1] = a0.y; av[2] = a0.z; av[3] = a0.w;
        av[4] = a1.x; av[5] = a1.y; av[6] = a1.z; av[7] = a1.w;
    }

    float mmax, lsum, accl, accr;
    {
        // self loop
        float4 l0 = *(const float4*)(rowv + j0);
        float4 l1 = *(const float4*)(rowv + j0 + 4);
        float4 t0 = *(const float4*)(&s_TyL[x1v][j0]);
        float4 t1 = *(const float4*)(&s_TyL[x1v][j0 + 4]);
        float4 w0 = *(const float4*)(&s_we[3][j0]);
        float4 w1 = *(const float4*)(&s_we[3][j0 + 4]);
        float p = 0.f;
        p += lrelu(l0.x + t0.x + xr[0] + w0.x) * av[0];
        p += lrelu(l0.y + t0.y + xr[1] + w0.y) * av[1];
        p += lrelu(l0.z + t0.z + xr[2] + w0.z) * av[2];
        p += lrelu(l0.w + t0.w + xr[3] + w0.w) * av[3];
        p += lrelu(l1.x + t1.x + xr[4] + w1.x) * av[4];
        p += lrelu(l1.y + t1.y + xr[5] + w1.y) * av[5];
        p += lrelu(l1.z + t1.z + xr[6] + w1.z) * av[6];
        p += lrelu(l1.w + t1.w + xr[7] + w1.w) * av[7];
        mmax = warp_sum(p);
        lsum = 1.f;
        accl = rowv[512 + lane] + s_TyL2[x1v][lane];
        accr = rowv[544 + lane] + s_TyR2[x1v][lane];
    }

    int p0 = d_rowptr[v], p1 = d_rowptr[v + 1];
    for (int p = p0; p < p1; p++) {
        int pk = d_csr1[p];
        int x0s = pk & 8191;
        int x1s = (pk >> 13) & 3;
        int t = pk >> 15;
        const float* rows = d_Cbuf + x0s * 576;
        float4 l0 = *(const float4*)(rows + j0);
        float4 l1 = *(const float4*)(rows + j0 + 4);
        float yl = rows[512 + lane] + s_TyL2[x1s][lane];
        float yr = rows[544 + lane] + s_TyR2[x1s][lane];
        float4 t0 = *(const float4*)(&s_TyL[x1s][j0]);
        float4 t1 = *(const float4*)(&s_TyL[x1s][j0 + 4]);
        float4 w0 = *(const float4*)(&s_we[t][j0]);
        float4 w1 = *(const float4*)(&s_we[t][j0 + 4]);
        float pp = 0.f;
        pp += lrelu(l0.x + t0.x + xr[0] + w0.x) * av[0];
        pp += lrelu(l0.y + t0.y + xr[1] + w0.y) * av[1];
        pp += lrelu(l0.z + t0.z + xr[2] + w0.z) * av[2];
        pp += lrelu(l0.w + t0.w + xr[3] + w0.w) * av[3];
        pp += lrelu(l1.x + t1.x + xr[4] + w1.x) * av[4];
        pp += lrelu(l1.y + t1.y + xr[5] + w1.y) * av[5];
        pp += lrelu(l1.z + t1.z + xr[6] + w1.z) * av[6];
        pp += lrelu(l1.w + t1.w + xr[7] + w1.w) * av[7];
        float e = warp_sum(pp);
        if (e > mmax) {
            float sc = __expf(mmax - e);
            lsum = lsum * sc + 1.f;
            accl = accl * sc + yl;
            accr = accr * sc + yr;
            mmax = e;
        } else {
            float w = __expf(e - mmax);
            lsum += w;
            accl += w * yl;
            accr += w * yr;
        }
    }
    float inv = 1.f / lsum;
    d_xl2[v * 32 + lane] = accl * inv + d_cl[lane];
    d_xr2[v * 32 + lane] = accr * inv + d_cr[lane];
}

// ---------------- layer 2 + global mean accumulation ----------------
__global__ void __launch_bounds__(256) k_edge2(const float* __restrict__ att2,
                                               const float* __restrict__ bias2, int n) {
    __shared__ float s_we[4][32];
    __shared__ float s_red[8][32];
    int tid = threadIdx.x;
    if (tid < 128) ((float*)s_we)[tid] = ((const float*)d_we2)[tid];
    __syncthreads();
    int lane = tid & 31, wid = tid >> 5;
    int v = blockIdx.x * 8 + wid;
    float hout = 0.f;
    if (v < n) {
        float xrv = d_xr2[v * 32 + lane];
        float a = att2[lane];
        float xlv = d_xl2[v * 32 + lane];
        float e0 = warp_sum(lrelu(xlv + xrv + s_we[3][lane]) * a);
        float mmax = e0, lsum = 1.f, acc = xlv;
        int p0 = d_rowptr[v], p1 = d_rowptr[v + 1];
        for (int p = p0; p < p1; p++) {
            int pk = d_csr2[p];
            int s = pk & 0xFFFFF, t = pk >> 20;
            float xls = d_xl2[s * 32 + lane];
            float e = warp_sum(lrelu(xls + xrv + s_we[t][lane]) * a);
            if (e > mmax) {
                float sc = __expf(mmax - e);
                lsum = lsum * sc + 1.f;
                acc = acc * sc + xls;
                mmax = e;
            } else {
                float w = __expf(e - mmax);
                lsum += w;
                acc += w * xls;
            }
        }
        hout = acc / lsum + bias2[lane];
    }
    s_red[wid][lane] = hout;
    __syncthreads();
    if (wid == 0) {
        float s = 0.f;
#pragma unroll
        for (int w = 0; w < 8; w++) s += s_red[w][lane];
        atomicAdd(&d_gsum[lane], s);
    }
}

// ---------------- final: policy head + softmax ----------------
__global__ void k_final(const float* __restrict__ pW, const float* __restrict__ pb,
                        float* __restrict__ out, float invN) {
    __shared__ float g[32];
    __shared__ float red[64];
    int t = threadIdx.x;  // 64 threads
    if (t < 32) g[t] = d_gsum[t] * invN;
    __syncthreads();
    float lg = pb[t];
    for (int j = 0; j < 32; j++) lg += g[j] * pW[j * 64 + t];
    red[t] = lg;
    __syncthreads();
    for (int o = 32; o > 0; o >>= 1) {
        if (t < o) red[t] = fmaxf(red[t], red[t + o]);
        __syncthreads();
    }
    float mx = red[0];
    __syncthreads();
    float ex = expf(lg - mx);
    red[t] = ex;
    __syncthreads();
    for (int o = 32; o > 0; o >>= 1) {
        if (t < o) red[t] += red[t + o];
        __syncthreads();
    }
    out[t] = ex / red[0];
}

// ---------------- launch ----------------
extern "C" void kernel_launch(void* const* d_in, const int* in_sizes, int n_in,
                              void* d_out, int out_size) {
    const int*   x         = (const int*)d_in[0];
    const int*   ei        = (const int*)d_in[1];
    const int*   eat       = (const int*)d_in[2];
    const float* text_emb  = (const float*)d_in[3];
    const float* type_emb  = (const float*)d_in[4];
    const float* flow_emb  = (const float*)d_in[5];
    const float* pos_table = (const float*)d_in[6];
    const float* pos_W     = (const float*)d_in[7];
    const float* pos_b     = (const float*)d_in[8];
    const float* c1_Wl  = (const float*)d_in[9];
    const float* c1_bl  = (const float*)d_in[10];
    const float* c1_Wr  = (const float*)d_in[11];
    const float* c1_br  = (const float*)d_in[12];
    const float* c1_We  = (const float*)d_in[13];
    const float* c1_att = (const float*)d_in[14];
    const float* c1_bias= (const float*)d_in[15];
    const float* c2_Wl  = (const float*)d_in[16];
    const float* c2_bl  = (const float*)d_in[17];
    const float* c2_Wr  = (const float*)d_in[18];
    const float* c2_br  = (const float*)d_in[19];
    const float* c2_We  = (const float*)d_in[20];
    const float* c2_att = (const float*)d_in[21];
    const float* c2_bias= (const float*)d_in[22];
    const float* pW     = (const float*)d_in[23];
    const float* pb     = (const float*)d_in[24];
    float* out = (float*)d_out;

    int N = in_sizes[0] / 2; if (N > NN) N = NN;
    int E = in_sizes[1] / 2; if (E > EE) E = EE;
    int Mt = in_sizes[3] / 64;

    int nb = (N + 255) / 256;
    int eb = (E + 255) / 256;
    int sb = (N + 1023) / 1024;
    int vb = (N + 7) / 8;

    k_zero<<<nb, 256>>>(N);
    k_px<<<nb, 256>>>(x, N);
    k_count<<<eb, 256>>>(ei, eat, E);
    k_scan1<<<sb, 1024>>>(N);
    k_scan2<<<1, 32>>>(sb);
    k_scan3<<<sb, 1024>>>(N);
    k_fill<<<eb, 256>>>(ei, eat, E);
    k_pre<<<1, 256>>>(pos_table, pos_W, pos_b, flow_emb, type_emb,
                      c1_Wl, c1_bl, c1_Wr, c1_br, c1_We, c2_We,
                      c2_Wl, c2_Wr, c1_bias, c2_bl, c2_br, E);
    k_prem<<<2, 256>>>(c1_Wl, c2_Wl, c2_Wr);
    dim3 g((Mt + 63) / 64, 9);
    k_tables<<<g, 256>>>(text_emb, Mt);
    k_edge1<<<vb, 256>>>(c1_att, N);
    k_edge2<<<vb, 256>>>(c2_att, c2_bias, N);
    k_final<<<1, 64>>>(pW, pb, out, 1.0f / (float)N);
}

// round 2
// speedup vs baseline: 1.1609x; 1.1609x over previous
#include <cuda_runtime.h>
#include <cuda_bf16.h>

#define NN 50000
#define EE 800000
#define MAXPOS 5120

// ---------------- device scratch ----------------
// Cbuf row per text-id (1280 bytes):
//   [0,512)    TL  : 256 bf16
//   [512,1024) TR  : 256 bf16
//   [1024,1280) interleaved (yl_d f32, yr_d f32) d=0..31  (TL2/TR2)
__device__ __align__(16) unsigned char d_Cbuf[7001 * 1280];
__device__ float d_Bpack[64 * 576];
__device__ float d_pe[128];
__device__ float d_ea[4][128];
__device__ float d_we1[4][256];
__device__ float d_we2[4][32];
__device__ float d_TyL[3][256];
__device__ float d_TyR[3][256];
__device__ float d_TyL2[3][32];
__device__ float d_TyR2[3][32];
__device__ float d_cl[32];
__device__ float d_cr[32];
__device__ int   d_cnt[4];
__device__ int   d_px[NN];
__device__ int   d_deg[NN];
__device__ int   d_rowptr[NN + 1];
__device__ int   d_cursor[NN + 1];
__device__ int   d_bsum[64];
__device__ int   d_csr1[EE];                    // x0s | x1s<<13 | t<<15
__device__ int   d_csr2[EE];                    // s | t<<20
__device__ __nv_bfloat16 d_xl2h[NN * 32];
__device__ float d_xr2f[NN * 32];
__device__ float d_gsum[32];

// ---------------- helpers ----------------
__device__ __forceinline__ float warp_sum(float v) {
#pragma unroll
    for (int o = 16; o > 0; o >>= 1) v += __shfl_xor_sync(0xffffffffu, v, o);
    return v;
}
__device__ __forceinline__ float lrelu(float x) {
    return fmaxf(x, 0.f) + 0.2f * fminf(x, 0.f);
}

// ---------------- init (zero + px fused) ----------------
__global__ void k_init(const int* __restrict__ x, int n) {
    int i = blockIdx.x * 256 + threadIdx.x;
    if (i < n) {
        d_deg[i] = 0;
        d_px[i] = x[2 * i] | (x[2 * i + 1] << 13);
    }
    if (i < 4)  d_cnt[i] = 0;
    if (i < 32) d_gsum[i] = 0.f;
}

__global__ void k_count(const int* __restrict__ ei, const int* __restrict__ ea, int E) {
    __shared__ int c[3];
    if (threadIdx.x < 3) c[threadIdx.x] = 0;
    __syncthreads();
    int e = blockIdx.x * 256 + threadIdx.x;
    if (e < E) {
        atomicAdd(&d_deg[ei[E + e]], 1);
        atomicAdd(&c[ea[2 * e]], 1);
    }
    __syncthreads();
    if (threadIdx.x < 3) atomicAdd(&d_cnt[threadIdx.x], c[threadIdx.x]);
}

__global__ void k_scan1(int n) {
    __shared__ int wsum[32];
    int i = blockIdx.x * 1024 + threadIdx.x;
    int lane = threadIdx.x & 31, wid = threadIdx.x >> 5;
    int x = (i < n) ? d_deg[i] : 0;
#pragma unroll
    for (int o = 1; o < 32; o <<= 1) {
        int y = __shfl_up_sync(0xffffffffu, x, o);
        if (lane >= o) x += y;
    }
    if (lane == 31) wsum[wid] = x;
    __syncthreads();
    if (wid == 0) {
        int s = wsum[lane];
#pragma unroll
        for (int o = 1; o < 32; o <<= 1) {
            int y = __shfl_up_sync(0xffffffffu, s, o);
            if (lane >= o) s += y;
        }
        wsum[lane] = s;
    }
    __syncthreads();
    int incl = x + (wid > 0 ? wsum[wid - 1] : 0);
    if (i < n) d_rowptr[i + 1] = incl;
    if (threadIdx.x == 1023) d_bsum[blockIdx.x] = incl;
}

__global__ void k_scan2(int nb) {
    if (threadIdx.x == 0 && blockIdx.x == 0) {
        int run = 0;
        for (int b = 0; b < nb; b++) { int t = d_bsum[b]; d_bsum[b] = run; run += t; }
    }
}

__global__ void k_scan3(int n) {
    int i = blockIdx.x * 1024 + threadIdx.x;
    int off = d_bsum[blockIdx.x];
    if (i < n) {
        int val = d_rowptr[i + 1] + off;
        d_rowptr[i + 1] = val;
        d_cursor[i + 1] = val;
    }
    if (i == 0) { d_rowptr[0] = 0; d_cursor[0] = 0; }
}

__global__ void k_fill(const int* __restrict__ ei, const int* __restrict__ ea, int E) {
    int e = blockIdx.x * 256 + threadIdx.x;
    if (e < E) {
        int s = ei[e];
        int d = ei[E + e];
        int t = ea[2 * e];
        int pos = atomicAdd(&d_cursor[d], 1);
        d_csr1[pos] = d_px[s] | (t << 15);
        d_csr2[pos] = s | (t << 20);
    }
}

// ---------------- precompute (block 0 = tables, blocks 1-2 = Wtop@W2) ----------------
__global__ void k_pre(const float* __restrict__ pos_table, const float* __restrict__ pos_W,
                      const float* __restrict__ pos_b, const float* __restrict__ flow_emb,
                      const float* __restrict__ type_emb,
                      const float* __restrict__ c1_Wl, const float* __restrict__ c1_bl,
                      const float* __restrict__ c1_Wr, const float* __restrict__ c1_br,
                      const float* __restrict__ c1_We, const float* __restrict__ c2_We,
                      const float* __restrict__ c2_Wl, const float* __restrict__ c2_Wr,
                      const float* __restrict__ c1_bias,
                      const float* __restrict__ c2_bl, const float* __restrict__ c2_br,
                      int E) {
    int t = threadIdx.x;  // 256 threads
    if (blockIdx.x > 0) {
        // M = Wl1_top @ (Wl2 or Wr2) -> Bpack cols [512,576)
        const float* W2 = (blockIdx.x == 1) ? c2_Wl : c2_Wr;
        for (int i = t; i < 2048; i += 256) {
            int k = i >> 5, c = i & 31;
            float s = 0.f;
            const float* wrow = c1_Wl + k * 256;
            for (int j = 0; j < 256; j++) s += wrow[j] * W2[j * 32 + c];
            d_Bpack[k * 576 + 512 + (blockIdx.x - 1) * 32 + c] = s;
        }
        return;
    }
    // pe = pos_table[MAXPOS] @ pos_W + pos_b  (pos is provably always MAXPOS)
    if (t < 128) {
        const float* pr = pos_table + MAXPOS * 128;
        float s = pos_b[t];
        for (int k = 0; k < 128; k++) s += pr[k] * pos_W[k * 128 + t];
        d_pe[t] = s;
    }
    __syncthreads();
    if (t < 128) {
        float pe = d_pe[t];
        float invE = 1.f / (float)E;
        for (int ty = 0; ty < 3; ty++) d_ea[ty][t] = flow_emb[ty * 128 + t] + pe;
        d_ea[3][t] = pe + ((float)d_cnt[0] * flow_emb[t] +
                           (float)d_cnt[1] * flow_emb[128 + t] +
                           (float)d_cnt[2] * flow_emb[256 + t]) * invE;
    }
    {
        for (int ty = 0; ty < 3; ty++) {
            float sl = c1_bl[t], sr = c1_br[t];
            for (int k = 0; k < 64; k++) {
                float te = type_emb[ty * 64 + k];
                sl += te * c1_Wl[(64 + k) * 256 + t];
                sr += te * c1_Wr[(64 + k) * 256 + t];
            }
            d_TyL[ty][t] = sl; d_TyR[ty][t] = sr;
        }
    }
    __syncthreads();
    {
        for (int ty = 0; ty < 4; ty++) {
            float s = 0.f;
            for (int k = 0; k < 128; k++) s += d_ea[ty][k] * c1_We[k * 256 + t];
            d_we1[ty][t] = s;
        }
    }
    if (t < 32) {
        for (int ty = 0; ty < 4; ty++) {
            float s = 0.f;
            for (int k = 0; k < 128; k++) s += d_ea[ty][k] * c2_We[k * 32 + t];
            d_we2[ty][t] = s;
        }
        float sl = c2_bl[t], sr = c2_br[t];
        for (int k = 0; k < 256; k++) {
            float b = c1_bias[k];
            sl += b * c2_Wl[k * 32 + t];
            sr += b * c2_Wr[k * 32 + t];
        }
        d_cl[t] = sl; d_cr[t] = sr;
    }
    __syncthreads();
    if (t < 96) {
        int ty = t >> 5, c = t & 31;
        float sl = 0.f, sr = 0.f;
        for (int k = 0; k < 256; k++) {
            float x = d_TyL[ty][k];
            sl += x * c2_Wl[k * 32 + c];
            sr += x * c2_Wr[k * 32 + c];
        }
        d_TyL2[ty][c] = sl; d_TyR2[ty][c] = sr;
    }
    for (int i = t; i < 64 * 512; i += 256) {
        int k = i >> 9, j = i & 511;
        d_Bpack[k * 576 + j] = (j < 256) ? c1_Wl[k * 256 + j] : c1_Wr[k * 256 + (j - 256)];
    }
}

// Cbuf = text_emb (Mt x 64) @ Bpack (64 x 576); cols [0,512) stored bf16, [512,576) f32 interleaved
__global__ void __launch_bounds__(256) k_tables(const float* __restrict__ A, int M) {
    __shared__ __align__(16) float As[64][64];
    __shared__ __align__(16) float Bs[64][64];
    int r0 = blockIdx.x * 64, c0 = blockIdx.y * 64;
    int tid = threadIdx.x;
    for (int idx = tid; idx < 4096; idx += 256) {
        int r = idx >> 6, k = idx & 63;
        As[r][k] = (r0 + r < M) ? A[(r0 + r) * 64 + k] : 0.f;
        Bs[r][k] = d_Bpack[r * 576 + c0 + k];
    }
    __syncthreads();
    int tx = tid & 15, ty = tid >> 4;
    float acc[4][4] = {};
#pragma unroll 4
    for (int k = 0; k < 64; k++) {
        float a0 = As[ty * 4 + 0][k], a1 = As[ty * 4 + 1][k];
        float a2 = As[ty * 4 + 2][k], a3 = As[ty * 4 + 3][k];
        float4 b = *(const float4*)&Bs[k][tx * 4];
        acc[0][0] += a0 * b.x; acc[0][1] += a0 * b.y; acc[0][2] += a0 * b.z; acc[0][3] += a0 * b.w;
        acc[1][0] += a1 * b.x; acc[1][1] += a1 * b.y; acc[1][2] += a1 * b.z; acc[1][3] += a1 * b.w;
        acc[2][0] += a2 * b.x; acc[2][1] += a2 * b.y; acc[2][2] += a2 * b.z; acc[2][3] += a2 * b.w;
        acc[3][0] += a3 * b.x; acc[3][1] += a3 * b.y; acc[3][2] += a3 * b.z; acc[3][3] += a3 * b.w;
    }
#pragma unroll
    for (int i = 0; i < 4; i++) {
        int r = r0 + ty * 4 + i;
        if (r >= M) continue;
        unsigned char* rowp = d_Cbuf + (size_t)r * 1280;
        if (c0 < 512) {
            __nv_bfloat162 p0 = __floats2bfloat162_rn(acc[i][0], acc[i][1]);
            __nv_bfloat162 p1 = __floats2bfloat162_rn(acc[i][2], acc[i][3]);
            __nv_bfloat162* dst = (__nv_bfloat162*)(rowp + (c0 + tx * 4) * 2);
            dst[0] = p0; dst[1] = p1;
        } else {
#pragma unroll
            for (int q = 0; q < 4; q++) {
                int jj = c0 + tx * 4 + q - 512;
                int dd = jj & 31, w = jj >> 5;
                *(float*)(rowp + 1024 + dd * 8 + w * 4) = acc[i][q];
            }
        }
    }
}

// ---------------- layer 1: one warp per dst, chunked CSR + 2-deep pipeline ----------------
__global__ void __launch_bounds__(256) k_edge1(const float* __restrict__ att, int n) {
    __shared__ float s_cmb[12][256];   // c = t*3 + x1s (t<3), 9+x1 for self-loop
    __shared__ float s_TyR[3][256];
    __shared__ float s_TyL2[3][32];
    __shared__ float s_TyR2[3][32];
    __shared__ float s_cl[32], s_cr[32];
    int tid = threadIdx.x;
    for (int i = tid; i < 12 * 256; i += 256) {
        int c = i >> 8, j = i & 255;
        int tt = (c < 9) ? (c / 3) : 3;
        int x1 = (c < 9) ? (c % 3) : (c - 9);
        s_cmb[c][j] = d_we1[tt][j] + d_TyL[x1][j];
    }
    for (int i = tid; i < 768; i += 256) ((float*)s_TyR)[i] = ((const float*)d_TyR)[i];
    if (tid < 96) {
        ((float*)s_TyL2)[tid] = ((const float*)d_TyL2)[tid];
        ((float*)s_TyR2)[tid] = ((const float*)d_TyR2)[tid];
    }
    if (tid < 32) { s_cl[tid] = d_cl[tid]; s_cr[tid] = d_cr[tid]; }
    __syncthreads();

    int lane = tid & 31;
    int v = blockIdx.x * 8 + (tid >> 5);
    if (v >= n) return;
    int j0 = lane * 8;

    int pv = d_px[v];
    int x0v = pv & 8191, x1v = pv >> 13;
    const unsigned char* rowv = d_Cbuf + (size_t)x0v * 1280;

    // xr = TR[x0v] + TyR[x1v]; av = att
    float xr[8], av[8];
    {
        uint4 raw = *(const uint4*)(rowv + 512 + (lane << 4));
        const __nv_bfloat162* h = (const __nv_bfloat162*)&raw;
#pragma unroll
        for (int q = 0; q < 4; q++) {
            float2 f = __bfloat1622float2(h[q]);
            xr[2 * q]     = f.x + s_TyR[x1v][j0 + 2 * q];
            xr[2 * q + 1] = f.y + s_TyR[x1v][j0 + 2 * q + 1];
        }
        float4 a0 = *(const float4*)(att + j0);
        float4 a1 = *(const float4*)(att + j0 + 4);
        av[0] = a0.x; av[1] = a0.y; av[2] = a0.z; av[3] = a0.w;
        av[4] = a1.x; av[5] = a1.y; av[6] = a1.z; av[7] = a1.w;
    }

    float mmax, lsum, accl, accr;
    {
        // self loop: TL[x0v] + xr + cmb[9+x1v]
        uint4 raw = *(const uint4*)(rowv + (lane << 4));
        float2 yv = *(const float2*)(rowv + 1024 + (lane << 3));
        const __nv_bfloat162* h = (const __nv_bfloat162*)&raw;
        const float* cmb = &s_cmb[9 + x1v][j0];
        float p = 0.f;
#pragma unroll
        for (int q = 0; q < 4; q++) {
            float2 f = __bfloat1622float2(h[q]);
            p += lrelu(f.x + xr[2 * q]     + cmb[2 * q])     * av[2 * q];
            p += lrelu(f.y + xr[2 * q + 1] + cmb[2 * q + 1]) * av[2 * q + 1];
        }
        mmax = warp_sum(p);
        lsum = 1.f;
        accl = yv.x + s_TyL2[x1v][lane];
        accr = yv.y + s_TyR2[x1v][lane];
    }

    int p0 = d_rowptr[v], p1 = d_rowptr[v + 1];
    for (int base = p0; base < p1; base += 32) {
        int idx = base + lane;
        int pkl = (idx < p1) ? d_csr1[idx] : 0;
        int cnt = min(32, p1 - base);
        // prime pipeline
        int pk = __shfl_sync(0xffffffffu, pkl, 0);
        const unsigned char* r = d_Cbuf + (size_t)(pk & 8191) * 1280;
        uint4 tl = *(const uint4*)(r + (lane << 4));
        float2 y = *(const float2*)(r + 1024 + (lane << 3));
        for (int k = 0; k < cnt; k++) {
            int pk_c = pk; uint4 tl_c = tl; float2 y_c = y;
            if (k + 1 < cnt) {
                pk = __shfl_sync(0xffffffffu, pkl, k + 1);
                const unsigned char* rn = d_Cbuf + (size_t)(pk & 8191) * 1280;
                tl = *(const uint4*)(rn + (lane << 4));
                y  = *(const float2*)(rn + 1024 + (lane << 3));
            }
            int x1s = (pk_c >> 13) & 3;
            int t   = pk_c >> 15;
            const float* cmb = &s_cmb[t * 3 + x1s][j0];
            const __nv_bfloat162* h = (const __nv_bfloat162*)&tl_c;
            float pp = 0.f;
#pragma unroll
            for (int q = 0; q < 4; q++) {
                float2 f = __bfloat1622float2(h[q]);
                pp += lrelu(f.x + xr[2 * q]     + cmb[2 * q])     * av[2 * q];
                pp += lrelu(f.y + xr[2 * q + 1] + cmb[2 * q + 1]) * av[2 * q + 1];
            }
            float e = warp_sum(pp);
            float yl = y_c.x + s_TyL2[x1s][lane];
            float yr = y_c.y + s_TyR2[x1s][lane];
            if (e > mmax) {
                float sc = __expf(mmax - e);
                lsum = lsum * sc + 1.f;
                accl = accl * sc + yl;
                accr = accr * sc + yr;
                mmax = e;
            } else {
                float w = __expf(e - mmax);
                lsum += w;
                accl += w * yl;
                accr += w * yr;
            }
        }
    }
    float inv = 1.f / lsum;
    d_xl2h[v * 32 + lane] = __float2bfloat16(accl * inv + s_cl[lane]);
    d_xr2f[v * 32 + lane] = accr * inv + s_cr[lane];
}

// ---------------- layer 2 + global mean ----------------
__global__ void __launch_bounds__(256) k_edge2(const float* __restrict__ att2,
                                               const float* __restrict__ bias2, int n) {
    __shared__ float s_we[4][32];
    __shared__ float s_red[8][32];
    int tid = threadIdx.x;
    if (tid < 128) ((float*)s_we)[tid] = ((const float*)d_we2)[tid];
    __syncthreads();
    int lane = tid & 31, wid = tid >> 5;
    int v = blockIdx.x * 8 + wid;
    float hout = 0.f;
    if (v < n) {
        float xrv = d_xr2f[v * 32 + lane];
        float a = att2[lane];
        float xlv = __bfloat162float(d_xl2h[v * 32 + lane]);
        float mmax = warp_sum(lrelu(xlv + xrv + s_we[3][lane]) * a);
        float lsum = 1.f, acc = xlv;
        int p0 = d_rowptr[v], p1 = d_rowptr[v + 1];
        for (int base = p0; base < p1; base += 32) {
            int idx = base + lane;
            int pkl = (idx < p1) ? d_csr2[idx] : 0;
            int cnt = min(32, p1 - base);
            int pk = __shfl_sync(0xffffffffu, pkl, 0);
            float xn = __bfloat162float(d_xl2h[(pk & 0xFFFFF) * 32 + lane]);
            for (int k = 0; k < cnt; k++) {
                int pk_c = pk; float xls = xn;
                if (k + 1 < cnt) {
                    pk = __shfl_sync(0xffffffffu, pkl, k + 1);
                    xn = __bfloat162float(d_xl2h[(pk & 0xFFFFF) * 32 + lane]);
                }
                int t = pk_c >> 20;
                float e = warp_sum(lrelu(xls + xrv + s_we[t][lane]) * a);
                if (e > mmax) {
                    float sc = __expf(mmax - e);
                    lsum = lsum * sc + 1.f;
                    acc = acc * sc + xls;
                    mmax = e;
                } else {
                    float w = __expf(e - mmax);
                    lsum += w;
                    acc += w * xls;
                }
            }
        }
        hout = acc / lsum + bias2[lane];
    }
    s_red[wid][lane] = hout;
    __syncthreads();
    if (wid == 0) {
        float s = 0.f;
#pragma unroll
        for (int w = 0; w < 8; w++) s += s_red[w][lane];
        atomicAdd(&d_gsum[lane], s);
    }
}

// ---------------- final: policy head + softmax ----------------
__global__ void k_final(const float* __restrict__ pW, const float* __restrict__ pb,
                        float* __restrict__ out, float invN) {
    __shared__ float g[32];
    __shared__ float red[64];
    int t = threadIdx.x;  // 64 threads
    if (t < 32) g[t] = d_gsum[t] * invN;
    __syncthreads();
    float lg = pb[t];
    for (int j = 0; j < 32; j++) lg += g[j] * pW[j * 64 + t];
    red[t] = lg;
    __syncthreads();
    for (int o = 32; o > 0; o >>= 1) {
        if (t < o) red[t] = fmaxf(red[t], red[t + o]);
        __syncthreads();
    }
    float mx = red[0];
    __syncthreads();
    float ex = expf(lg - mx);
    red[t] = ex;
    __syncthreads();
    for (int o = 32; o > 0; o >>= 1) {
        if (t < o) red[t] += red[t + o];
        __syncthreads();
    }
    out[t] = ex / red[0];
}

// ---------------- launch ----------------
extern "C" void kernel_launch(void* const* d_in, const int* in_sizes, int n_in,
                              void* d_out, int out_size) {
    const int*   x         = (const int*)d_in[0];
    const int*   ei        = (const int*)d_in[1];
    const int*   eat       = (const int*)d_in[2];
    const float* text_emb  = (const float*)d_in[3];
    const float* type_emb  = (const float*)d_in[4];
    const float* flow_emb  = (const float*)d_in[5];
    const float* pos_table = (const float*)d_in[6];
    const float* pos_W     = (const float*)d_in[7];
    const float* pos_b     = (const float*)d_in[8];
    const float* c1_Wl  = (const float*)d_in[9];
    const float* c1_bl  = (const float*)d_in[10];
    const float* c1_Wr  = (const float*)d_in[11];
    const float* c1_br  = (const float*)d_in[12];
    const float* c1_We  = (const float*)d_in[13];
    const float* c1_att = (const float*)d_in[14];
    const float* c1_bias= (const float*)d_in[15];
    const float* c2_Wl  = (const float*)d_in[16];
    const float* c2_bl  = (const float*)d_in[17];
    const float* c2_Wr  = (const float*)d_in[18];
    const float* c2_br  = (const float*)d_in[19];
    const float* c2_We  = (const float*)d_in[20];
    const float* c2_att = (const float*)d_in[21];
    const float* c2_bias= (const float*)d_in[22];
    const float* pW     = (const float*)d_in[23];
    const float* pb     = (const float*)d_in[24];
    float* out = (float*)d_out;

    int N = in_sizes[0] / 2; if (N > NN) N = NN;
    int E = in_sizes[1] / 2; if (E > EE) E = EE;
    int Mt = in_sizes[3] / 64;

    int nb = (N + 255) / 256;
    int eb = (E + 255) / 256;
    int sb = (N + 1023) / 1024;
    int vb = (N + 7) / 8;

    k_init<<<nb, 256>>>(x, N);
    k_count<<<eb, 256>>>(ei, eat, E);
    k_scan1<<<sb, 1024>>>(N);
    k_scan2<<<1, 32>>>(sb);
    k_scan3<<<sb, 1024>>>(N);
    k_fill<<<eb, 256>>>(ei, eat, E);
    k_pre<<<3, 256>>>(pos_table, pos_W, pos_b, flow_emb, type_emb,
                      c1_Wl, c1_bl, c1_Wr, c1_br, c1_We, c2_We,
                      c2_Wl, c2_Wr, c1_bias, c2_bl, c2_br, E);
    dim3 g((Mt + 63) / 64, 9);
    k_tables<<<g, 256>>>(text_emb, Mt);
    k_edge1<<<vb, 256>>>(c1_att, N);
    k_edge2<<<vb, 256>>>(c2_att, c2_bias, N);
    k_final<<<1, 64>>>(pW, pb, out, 1.0f / (float)N);
}

// round 3
// speedup vs baseline: 1.1828x; 1.0188x over previous
#include <cuda_runtime.h>
#include <cuda_bf16.h>

#define NN 50000
#define EE 800000
#define MAXPOS 5120

// ---------------- device scratch ----------------
// Cbuf row per text-id (1280 bytes):
//   [0,512)    TL  : 256 bf16
//   [512,1024) TR  : 256 bf16
//   [1024,1280) interleaved (yl_d f32, yr_d f32) d=0..31  (TL2/TR2)
__device__ __align__(16) unsigned char d_Cbuf[7001 * 1280];
__device__ float d_Bpack[64 * 576];
__device__ float d_pe[128];
__device__ float d_ea[4][128];
__device__ float d_we1[4][256];
__device__ float d_we2[4][32];
__device__ float d_TyL[3][256];
__device__ float d_TyR[3][256];
__device__ float d_TyL2[3][32];
__device__ float d_TyR2[3][32];
__device__ float d_cl[32];
__device__ float d_cr[32];
__device__ int   d_cnt[4];
__device__ int   d_px[NN];
__device__ int   d_deg[NN];
__device__ int   d_rowptr[NN + 1];
__device__ int   d_cursor[NN + 1];
__device__ int   d_bsum[64];
__device__ int   d_csr1[EE];                    // x0s | x1s<<13 | t<<15
__device__ int   d_csr2[EE];                    // s | t<<20
__device__ __nv_bfloat16 d_xl2h[NN * 32];
__device__ float d_xr2f[NN * 32];
__device__ float d_gsum[32];

// ---------------- helpers ----------------
__device__ __forceinline__ float warp_sum(float v) {
#pragma unroll
    for (int o = 16; o > 0; o >>= 1) v += __shfl_xor_sync(0xffffffffu, v, o);
    return v;
}
__device__ __forceinline__ float warp_max(float v) {
#pragma unroll
    for (int o = 16; o > 0; o >>= 1) v = fmaxf(v, __shfl_xor_sync(0xffffffffu, v, o));
    return v;
}
__device__ __forceinline__ float lrelu(float x) {
    return fmaxf(x, 0.f) + 0.2f * fminf(x, 0.f);
}

// ---------------- init ----------------
__global__ void k_init(const int* __restrict__ x, int n) {
    int i = blockIdx.x * 256 + threadIdx.x;
    if (i < n) {
        d_deg[i] = 0;
        d_px[i] = x[2 * i] | (x[2 * i + 1] << 13);
    }
    if (i < 4)  d_cnt[i] = 0;
    if (i < 32) d_gsum[i] = 0.f;
}

__global__ void k_count(const int* __restrict__ ei, const int* __restrict__ ea, int E) {
    __shared__ int c[3];
    if (threadIdx.x < 3) c[threadIdx.x] = 0;
    __syncthreads();
    int e = blockIdx.x * 256 + threadIdx.x;
    if (e < E) {
        atomicAdd(&d_deg[ei[E + e]], 1);
        atomicAdd(&c[ea[2 * e]], 1);
    }
    __syncthreads();
    if (threadIdx.x < 3) atomicAdd(&d_cnt[threadIdx.x], c[threadIdx.x]);
}

__global__ void k_scan1(int n) {
    __shared__ int wsum[32];
    int i = blockIdx.x * 1024 + threadIdx.x;
    int lane = threadIdx.x & 31, wid = threadIdx.x >> 5;
    int x = (i < n) ? d_deg[i] : 0;
#pragma unroll
    for (int o = 1; o < 32; o <<= 1) {
        int y = __shfl_up_sync(0xffffffffu, x, o);
        if (lane >= o) x += y;
    }
    if (lane == 31) wsum[wid] = x;
    __syncthreads();
    if (wid == 0) {
        int s = wsum[lane];
#pragma unroll
        for (int o = 1; o < 32; o <<= 1) {
            int y = __shfl_up_sync(0xffffffffu, s, o);
            if (lane >= o) s += y;
        }
        wsum[lane] = s;
    }
    __syncthreads();
    int incl = x + (wid > 0 ? wsum[wid - 1] : 0);
    if (i < n) d_rowptr[i + 1] = incl;
    if (threadIdx.x == 1023) d_bsum[blockIdx.x] = incl;
}

__global__ void k_scan2(int nb) {
    __shared__ int s[64];
    int t = threadIdx.x;  // 64 threads
    int orig = (t < nb) ? d_bsum[t] : 0;
    s[t] = orig;
    __syncthreads();
#pragma unroll
    for (int o = 1; o < 64; o <<= 1) {
        int v = (t >= o) ? s[t - o] : 0;
        __syncthreads();
        s[t] += v;
        __syncthreads();
    }
    if (t < nb) d_bsum[t] = s[t] - orig;
}

__global__ void k_scan3(int n) {
    int i = blockIdx.x * 1024 + threadIdx.x;
    int off = d_bsum[blockIdx.x];
    if (i < n) {
        int val = d_rowptr[i + 1] + off;
        d_rowptr[i + 1] = val;
        d_cursor[i + 1] = val;
    }
    if (i == 0) { d_rowptr[0] = 0; d_cursor[0] = 0; }
}

__global__ void k_fill(const int* __restrict__ ei, const int* __restrict__ ea, int E) {
    int e = blockIdx.x * 256 + threadIdx.x;
    if (e < E) {
        int s = ei[e];
        int d = ei[E + e];
        int t = ea[2 * e];
        int pos = atomicAdd(&d_cursor[d], 1);
        d_csr1[pos] = d_px[s] | (t << 15);
        d_csr2[pos] = s | (t << 20);
    }
}

// ---------------- precompute ----------------
__global__ void k_pre(const float* __restrict__ pos_table, const float* __restrict__ pos_W,
                      const float* __restrict__ pos_b, const float* __restrict__ flow_emb,
                      const float* __restrict__ type_emb,
                      const float* __restrict__ c1_Wl, const float* __restrict__ c1_bl,
                      const float* __restrict__ c1_Wr, const float* __restrict__ c1_br,
                      const float* __restrict__ c1_We, const float* __restrict__ c2_We,
                      const float* __restrict__ c2_Wl, const float* __restrict__ c2_Wr,
                      const float* __restrict__ c1_bias,
                      const float* __restrict__ c2_bl, const float* __restrict__ c2_br,
                      int E) {
    int t = threadIdx.x;  // 256 threads
    if (blockIdx.x > 0) {
        const float* W2 = (blockIdx.x == 1) ? c2_Wl : c2_Wr;
        for (int i = t; i < 2048; i += 256) {
            int k = i >> 5, c = i & 31;
            float s = 0.f;
            const float* wrow = c1_Wl + k * 256;
            for (int j = 0; j < 256; j++) s += wrow[j] * W2[j * 32 + c];
            d_Bpack[k * 576 + 512 + (blockIdx.x - 1) * 32 + c] = s;
        }
        return;
    }
    if (t < 128) {
        const float* pr = pos_table + MAXPOS * 128;
        float s = pos_b[t];
        for (int k = 0; k < 128; k++) s += pr[k] * pos_W[k * 128 + t];
        d_pe[t] = s;
    }
    __syncthreads();
    if (t < 128) {
        float pe = d_pe[t];
        float invE = 1.f / (float)E;
        for (int ty = 0; ty < 3; ty++) d_ea[ty][t] = flow_emb[ty * 128 + t] + pe;
        d_ea[3][t] = pe + ((float)d_cnt[0] * flow_emb[t] +
                           (float)d_cnt[1] * flow_emb[128 + t] +
                           (float)d_cnt[2] * flow_emb[256 + t]) * invE;
    }
    {
        for (int ty = 0; ty < 3; ty++) {
            float sl = c1_bl[t], sr = c1_br[t];
            for (int k = 0; k < 64; k++) {
                float te = type_emb[ty * 64 + k];
                sl += te * c1_Wl[(64 + k) * 256 + t];
                sr += te * c1_Wr[(64 + k) * 256 + t];
            }
            d_TyL[ty][t] = sl; d_TyR[ty][t] = sr;
        }
    }
    __syncthreads();
    {
        for (int ty = 0; ty < 4; ty++) {
            float s = 0.f;
            for (int k = 0; k < 128; k++) s += d_ea[ty][k] * c1_We[k * 256 + t];
            d_we1[ty][t] = s;
        }
    }
    if (t < 32) {
        for (int ty = 0; ty < 4; ty++) {
            float s = 0.f;
            for (int k = 0; k < 128; k++) s += d_ea[ty][k] * c2_We[k * 32 + t];
            d_we2[ty][t] = s;
        }
        float sl = c2_bl[t], sr = c2_br[t];
        for (int k = 0; k < 256; k++) {
            float b = c1_bias[k];
            sl += b * c2_Wl[k * 32 + t];
            sr += b * c2_Wr[k * 32 + t];
        }
        d_cl[t] = sl; d_cr[t] = sr;
    }
    __syncthreads();
    if (t < 96) {
        int ty = t >> 5, c = t & 31;
        float sl = 0.f, sr = 0.f;
        for (int k = 0; k < 256; k++) {
            float x = d_TyL[ty][k];
            sl += x * c2_Wl[k * 32 + c];
            sr += x * c2_Wr[k * 32 + c];
        }
        d_TyL2[ty][c] = sl; d_TyR2[ty][c] = sr;
    }
    for (int i = t; i < 64 * 512; i += 256) {
        int k = i >> 9, j = i & 511;
        d_Bpack[k * 576 + j] = (j < 256) ? c1_Wl[k * 256 + j] : c1_Wr[k * 256 + (j - 256)];
    }
}

// Cbuf = text_emb (Mt x 64) @ Bpack (64 x 576)
__global__ void __launch_bounds__(256) k_tables(const float* __restrict__ A, int M) {
    __shared__ __align__(16) float As[64][64];
    __shared__ __align__(16) float Bs[64][64];
    int r0 = blockIdx.x * 64, c0 = blockIdx.y * 64;
    int tid = threadIdx.x;
    for (int idx = tid; idx < 4096; idx += 256) {
        int r = idx >> 6, k = idx & 63;
        As[r][k] = (r0 + r < M) ? A[(r0 + r) * 64 + k] : 0.f;
        Bs[r][k] = d_Bpack[r * 576 + c0 + k];
    }
    __syncthreads();
    int tx = tid & 15, ty = tid >> 4;
    float acc[4][4] = {};
#pragma unroll 4
    for (int k = 0; k < 64; k++) {
        float a0 = As[ty * 4 + 0][k], a1 = As[ty * 4 + 1][k];
        float a2 = As[ty * 4 + 2][k], a3 = As[ty * 4 + 3][k];
        float4 b = *(const float4*)&Bs[k][tx * 4];
        acc[0][0] += a0 * b.x; acc[0][1] += a0 * b.y; acc[0][2] += a0 * b.z; acc[0][3] += a0 * b.w;
        acc[1][0] += a1 * b.x; acc[1][1] += a1 * b.y; acc[1][2] += a1 * b.z; acc[1][3] += a1 * b.w;
        acc[2][0] += a2 * b.x; acc[2][1] += a2 * b.y; acc[2][2] += a2 * b.z; acc[2][3] += a2 * b.w;
        acc[3][0] += a3 * b.x; acc[3][1] += a3 * b.y; acc[3][2] += a3 * b.z; acc[3][3] += a3 * b.w;
    }
#pragma unroll
    for (int i = 0; i < 4; i++) {
        int r = r0 + ty * 4 + i;
        if (r >= M) continue;
        unsigned char* rowp = d_Cbuf + (size_t)r * 1280;
        if (c0 < 512) {
            __nv_bfloat162 p0 = __floats2bfloat162_rn(acc[i][0], acc[i][1]);
            __nv_bfloat162 p1 = __floats2bfloat162_rn(acc[i][2], acc[i][3]);
            __nv_bfloat162* dst = (__nv_bfloat162*)(rowp + (c0 + tx * 4) * 2);
            dst[0] = p0; dst[1] = p1;
        } else {
#pragma unroll
            for (int q = 0; q < 4; q++) {
                int jj = c0 + tx * 4 + q - 512;
                int dd = jj & 31, w = jj >> 5;
                *(float*)(rowp + 1024 + dd * 8 + w * 4) = acc[i][q];
            }
        }
    }
}

// ---------------- layer 1: warp/dst, two-phase chunks (scores then aggregate) ----------------
__global__ void __launch_bounds__(256) k_edge1(const float* __restrict__ att, int n) {
    __shared__ float s_cmb[12][256];   // c = t*3 + x1s (t<3), 9+x1 for self-loop
    __shared__ float s_TyR[3][256];
    __shared__ float s_TyL2[3][32];
    __shared__ float s_TyR2[3][32];
    __shared__ float s_cl[32], s_cr[32];
    int tid = threadIdx.x;
    for (int i = tid; i < 12 * 256; i += 256) {
        int c = i >> 8, j = i & 255;
        int tt = (c < 9) ? (c / 3) : 3;
        int x1 = (c < 9) ? (c % 3) : (c - 9);
        s_cmb[c][j] = d_we1[tt][j] + d_TyL[x1][j];
    }
    for (int i = tid; i < 768; i += 256) {
        ((float*)s_TyR)[i] = ((const float*)d_TyR)[i];
    }
    if (tid < 96) {
        ((float*)s_TyL2)[tid] = ((const float*)d_TyL2)[tid];
        ((float*)s_TyR2)[tid] = ((const float*)d_TyR2)[tid];
    }
    if (tid < 32) { s_cl[tid] = d_cl[tid]; s_cr[tid] = d_cr[tid]; }
    __syncthreads();

    int lane = tid & 31;
    int v = blockIdx.x * 8 + (tid >> 5);
    if (v >= n) return;
    int j0 = lane * 8;

    int pv = d_px[v];
    int x0v = pv & 8191, x1v = pv >> 13;
    const unsigned char* rowv = d_Cbuf + (size_t)x0v * 1280;

    float xr[8], av[8];
    {
        uint4 raw = *(const uint4*)(rowv + 512 + (lane << 4));
        const __nv_bfloat162* h = (const __nv_bfloat162*)&raw;
#pragma unroll
        for (int q = 0; q < 4; q++) {
            float2 f = __bfloat1622float2(h[q]);
            xr[2 * q]     = f.x + s_TyR[x1v][j0 + 2 * q];
            xr[2 * q + 1] = f.y + s_TyR[x1v][j0 + 2 * q + 1];
        }
        float4 a0 = *(const float4*)(att + j0);
        float4 a1 = *(const float4*)(att + j0 + 4);
        av[0] = a0.x; av[1] = a0.y; av[2] = a0.z; av[3] = a0.w;
        av[4] = a1.x; av[5] = a1.y; av[6] = a1.z; av[7] = a1.w;
    }

    float mmax, lsum, accl, accr;
    {
        uint4 raw = *(const uint4*)(rowv + (lane << 4));
        float2 yv = *(const float2*)(rowv + 1024 + (lane << 3));
        const __nv_bfloat162* h = (const __nv_bfloat162*)&raw;
        const float* cmb = &s_cmb[9 + x1v][j0];
        float p = 0.f;
#pragma unroll
        for (int q = 0; q < 4; q++) {
            float2 f = __bfloat1622float2(h[q]);
            p += lrelu(f.x + xr[2 * q]     + cmb[2 * q])     * av[2 * q];
            p += lrelu(f.y + xr[2 * q + 1] + cmb[2 * q + 1]) * av[2 * q + 1];
        }
        mmax = warp_sum(p);
        lsum = 1.f;
        accl = yv.x + s_TyL2[x1v][lane];
        accr = yv.y + s_TyR2[x1v][lane];
    }

    int p0 = d_rowptr[v], p1 = d_rowptr[v + 1];
    for (int base = p0; base < p1; base += 32) {
        int idx = base + lane;
        int pkl = (idx < p1) ? d_csr1[idx] : 0;
        int cnt = min(32, p1 - base);

        // ---- phase A: scores (only max + lane-stash carried) ----
        float myscore = -1e30f;
        int pk = __shfl_sync(0xffffffffu, pkl, 0);
        uint4 tl = *(const uint4*)(d_Cbuf + (size_t)(pk & 8191) * 1280 + (lane << 4));
        for (int k = 0; k < cnt; k++) {
            int pk_c = pk; uint4 tl_c = tl;
            if (k + 1 < cnt) {
                pk = __shfl_sync(0xffffffffu, pkl, k + 1);
                tl = *(const uint4*)(d_Cbuf + (size_t)(pk & 8191) * 1280 + (lane << 4));
            }
            int x1s = (pk_c >> 13) & 3;
            int t   = pk_c >> 15;
            const float* cmb = &s_cmb[t * 3 + x1s][j0];
            const __nv_bfloat162* h = (const __nv_bfloat162*)&tl_c;
            float pp = 0.f;
#pragma unroll
            for (int q = 0; q < 4; q++) {
                float2 f = __bfloat1622float2(h[q]);
                pp += lrelu(f.x + xr[2 * q]     + cmb[2 * q])     * av[2 * q];
                pp += lrelu(f.y + xr[2 * q + 1] + cmb[2 * q + 1]) * av[2 * q + 1];
            }
            float e = warp_sum(pp);
            myscore = (lane == k) ? e : myscore;
        }

        // ---- chunk-batched softmax update (one exp for 32 edges) ----
        float cmax = warp_max(myscore);
        float nm = fmaxf(mmax, cmax);
        float sc = __expf(mmax - nm);
        float w  = __expf(myscore - nm);   // 0 for invalid lanes
        float wsum = warp_sum(w);
        lsum = lsum * sc + wsum;
        accl *= sc; accr *= sc;
        mmax = nm;

        // ---- phase B: weighted aggregation (FFMA-only chain) ----
        int pk2 = __shfl_sync(0xffffffffu, pkl, 0);
        float2 y = *(const float2*)(d_Cbuf + (size_t)(pk2 & 8191) * 1280 + 1024 + (lane << 3));
        for (int k = 0; k < cnt; k++) {
            int pk_c = pk2; float2 y_c = y;
            if (k + 1 < cnt) {
                pk2 = __shfl_sync(0xffffffffu, pkl, k + 1);
                y = *(const float2*)(d_Cbuf + (size_t)(pk2 & 8191) * 1280 + 1024 + (lane << 3));
            }
            float wk = __shfl_sync(0xffffffffu, w, k);
            int x1s = (pk_c >> 13) & 3;
            float yl = y_c.x + s_TyL2[x1s][lane];
            float yr = y_c.y + s_TyR2[x1s][lane];
            accl += wk * yl;
            accr += wk * yr;
        }
    }
    float inv = 1.f / lsum;
    d_xl2h[v * 32 + lane] = __float2bfloat16(accl * inv + s_cl[lane]);
    d_xr2f[v * 32 + lane] = accr * inv + s_cr[lane];
}

// ---------------- layer 2 + global mean (two-phase, smem stash) ----------------
__global__ void __launch_bounds__(256) k_edge2(const float* __restrict__ att2,
                                               const float* __restrict__ bias2, int n) {
    __shared__ float s_we[4][32];
    __shared__ float s_red[8][32];
    __shared__ float s_stash[8][32][32];   // [warp][k][lane]
    int tid = threadIdx.x;
    if (tid < 128) ((float*)s_we)[tid] = ((const float*)d_we2)[tid];
    __syncthreads();
    int lane = tid & 31, wid = tid >> 5;
    int v = blockIdx.x * 8 + wid;
    float hout = 0.f;
    if (v < n) {
        float xrv = d_xr2f[v * 32 + lane];
        float a = att2[lane];
        float xlv = __bfloat162float(d_xl2h[v * 32 + lane]);
        float mmax = warp_sum(lrelu(xlv + xrv + s_we[3][lane]) * a);
        float lsum = 1.f, acc = xlv;
        int p0 = d_rowptr[v], p1 = d_rowptr[v + 1];
        for (int base = p0; base < p1; base += 32) {
            int idx = base + lane;
            int pkl = (idx < p1) ? d_csr2[idx] : 0;
            int cnt = min(32, p1 - base);

            // phase A: scores + stash xls
            float myscore = -1e30f;
            int pk = __shfl_sync(0xffffffffu, pkl, 0);
            float xn = __bfloat162float(d_xl2h[(pk & 0xFFFFF) * 32 + lane]);
            for (int k = 0; k < cnt; k++) {
                int pk_c = pk; float xls = xn;
                if (k + 1 < cnt) {
                    pk = __shfl_sync(0xffffffffu, pkl, k + 1);
                    xn = __bfloat162float(d_xl2h[(pk & 0xFFFFF) * 32 + lane]);
                }
                s_stash[wid][k][lane] = xls;
                int t = pk_c >> 20;
                float e = warp_sum(lrelu(xls + xrv + s_we[t][lane]) * a);
                myscore = (lane == k) ? e : myscore;
            }

            // batched update
            float cmax = warp_max(myscore);
            float nm = fmaxf(mmax, cmax);
            float sc = __expf(mmax - nm);
            float w  = __expf(myscore - nm);
            float wsum = warp_sum(w);
            lsum = lsum * sc + wsum;
            acc *= sc;
            mmax = nm;

            // phase B: accumulate from smem stash
            for (int k = 0; k < cnt; k++) {
                float wk = __shfl_sync(0xffffffffu, w, k);
                acc += wk * s_stash[wid][k][lane];
            }
        }
        hout = acc / lsum + bias2[lane];
    }
    s_red[wid][lane] = hout;
    __syncthreads();
    if (wid == 0) {
        float s = 0.f;
#pragma unroll
        for (int w = 0; w < 8; w++) s += s_red[w][lane];
        atomicAdd(&d_gsum[lane], s);
    }
}

// ---------------- final: policy head + softmax ----------------
__global__ void k_final(const float* __restrict__ pW, const float* __restrict__ pb,
                        float* __restrict__ out, float invN) {
    __shared__ float g[32];
    __shared__ float red[64];
    int t = threadIdx.x;  // 64 threads
    if (t < 32) g[t] = d_gsum[t] * invN;
    __syncthreads();
    float lg = pb[t];
    for (int j = 0; j < 32; j++) lg += g[j] * pW[j * 64 + t];
    red[t] = lg;
    __syncthreads();
    for (int o = 32; o > 0; o >>= 1) {
        if (t < o) red[t] = fmaxf(red[t], red[t + o]);
        __syncthreads();
    }
    float mx = red[0];
    __syncthreads();
    float ex = expf(lg - mx);
    red[t] = ex;
    __syncthreads();
    for (int o = 32; o > 0; o >>= 1) {
        if (t < o) red[t] += red[t + o];
        __syncthreads();
    }
    out[t] = ex / red[0];
}

// ---------------- launch ----------------
extern "C" void kernel_launch(void* const* d_in, const int* in_sizes, int n_in,
                              void* d_out, int out_size) {
    const int*   x         = (const int*)d_in[0];
    const int*   ei        = (const int*)d_in[1];
    const int*   eat       = (const int*)d_in[2];
    const float* text_emb  = (const float*)d_in[3];
    const float* type_emb  = (const float*)d_in[4];
    const float* flow_emb  = (const float*)d_in[5];
    const float* pos_table = (const float*)d_in[6];
    const float* pos_W     = (const float*)d_in[7];
    const float* pos_b     = (const float*)d_in[8];
    const float* c1_Wl  = (const float*)d_in[9];
    const float* c1_bl  = (const float*)d_in[10];
    const float* c1_Wr  = (const float*)d_in[11];
    const float* c1_br  = (const float*)d_in[12];
    const float* c1_We  = (const float*)d_in[13];
    const float* c1_att = (const float*)d_in[14];
    const float* c1_bias= (const float*)d_in[15];
    const float* c2_Wl  = (const float*)d_in[16];
    const float* c2_bl  = (const float*)d_in[17];
    const float* c2_Wr  = (const float*)d_in[18];
    const float* c2_br  = (const float*)d_in[19];
    const float* c2_We  = (const float*)d_in[20];
    const float* c2_att = (const float*)d_in[21];
    const float* c2_bias= (const float*)d_in[22];
    const float* pW     = (const float*)d_in[23];
    const float* pb     = (const float*)d_in[24];
    float* out = (float*)d_out;

    int N = in_sizes[0] / 2; if (N > NN) N = NN;
    int E = in_sizes[1] / 2; if (E > EE) E = EE;
    int Mt = in_sizes[3] / 64;

    int nb = (N + 255) / 256;
    int eb = (E + 255) / 256;
    int sb = (N + 1023) / 1024;
    int vb = (N + 7) / 8;

    k_init<<<nb, 256>>>(x, N);
    k_count<<<eb, 256>>>(ei, eat, E);
    k_scan1<<<sb, 1024>>>(N);
    k_scan2<<<1, 64>>>(sb);
    k_scan3<<<sb, 1024>>>(N);
    k_fill<<<eb, 256>>>(ei, eat, E);
    k_pre<<<3, 256>>>(pos_table, pos_W, pos_b, flow_emb, type_emb,
                      c1_Wl, c1_bl, c1_Wr, c1_br, c1_We, c2_We,
                      c2_Wl, c2_Wr, c1_bias, c2_bl, c2_br, E);
    dim3 g((Mt + 63) / 64, 9);
    k_tables<<<g, 256>>>(text_emb, Mt);
    k_edge1<<<vb, 256>>>(c1_att, N);
    k_edge2<<<vb, 256>>>(c2_att, c2_bias, N);
    k_final<<<1, 64>>>(pW, pb, out, 1.0f / (float)N);
}